// round 9
// baseline (speedup 1.0000x reference)
#include <cuda_runtime.h>
#include <cuda_bf16.h>
#include <cstdint>

#define BIGV 10000000000.0f
#define F_L2E 1.4426950408889634f
#define F_LN2 0.6931471805599453f

// D (pre-scaled by log2(e)) in anti-diagonal-major layout:
// g_D[b][kd][i0] = log2e * D[b][i0][j0], kd = i0 + j0 (0-based), dims [64][1024][512].
__device__ float g_D[(size_t)64 * 1024 * 512];

__device__ __forceinline__ float ex2f_(float x) {
    float r; asm("ex2.approx.f32 %0, %1;" : "=f"(r) : "f"(x)); return r;
}
__device__ __forceinline__ float lg2f_(float x) {
    float r; asm("lg2.approx.f32 %0, %1;" : "=f"(r) : "f"(x)); return r;
}
__device__ __forceinline__ void st_release_shared(int* p, int v) {
    unsigned a = (unsigned)__cvta_generic_to_shared(p);
    asm volatile("st.release.cta.shared.b32 [%0], %1;" :: "r"(a), "r"(v) : "memory");
}
__device__ __forceinline__ int ld_acquire_shared(const int* p) {
    unsigned a = (unsigned)__cvta_generic_to_shared(p);
    int v; asm volatile("ld.acquire.cta.shared.b32 %0, [%1];" : "=r"(v) : "r"(a) : "memory");
    return v;
}

// ---------------------------------------------------------------------------
// Kernel 1: squared distances * log2e, written anti-diagonal-major.
// ---------------------------------------------------------------------------
__global__ __launch_bounds__(256) void sqdist_kernel(const float* __restrict__ x,
                                                     const float* __restrict__ y)
{
    __shared__ __align__(16) float xs[16][64];
    __shared__ __align__(16) float ys[16][64];
    __shared__ float x2s[64], y2s[64];
    __shared__ float ts[64][66];

    const int b   = blockIdx.z;
    const int i0  = blockIdx.y * 64;
    const int j0  = blockIdx.x * 64;
    const int tid = threadIdx.x;

    {
        int row = tid >> 2;
        int d0  = (tid & 3) * 4;
        float4 xv = *(const float4*)(x + ((size_t)(b * 512 + i0 + row)) * 16 + d0);
        xs[d0 + 0][row] = xv.x; xs[d0 + 1][row] = xv.y;
        xs[d0 + 2][row] = xv.z; xs[d0 + 3][row] = xv.w;
        float4 yv = *(const float4*)(y + ((size_t)(b * 512 + j0 + row)) * 16 + d0);
        ys[d0 + 0][row] = yv.x; ys[d0 + 1][row] = yv.y;
        ys[d0 + 2][row] = yv.z; ys[d0 + 3][row] = yv.w;
    }
    __syncthreads();

    if (tid < 64) {
        float s = 0.f;
        #pragma unroll
        for (int d = 0; d < 16; d++) s += xs[d][tid] * xs[d][tid];
        x2s[tid] = s;
    } else if (tid < 128) {
        int c = tid - 64;
        float s = 0.f;
        #pragma unroll
        for (int d = 0; d < 16; d++) s += ys[d][c] * ys[d][c];
        y2s[c] = s;
    }
    __syncthreads();

    const int tx = tid & 15;
    const int ty = tid >> 4;
    float acc[4][4];
    #pragma unroll
    for (int r = 0; r < 4; r++)
        #pragma unroll
        for (int c = 0; c < 4; c++) acc[r][c] = 0.f;

    #pragma unroll
    for (int d = 0; d < 16; d++) {
        float4 av = *(const float4*)&xs[d][ty * 4];
        float4 bv = *(const float4*)&ys[d][tx * 4];
        float a[4]  = {av.x, av.y, av.z, av.w};
        float bb[4] = {bv.x, bv.y, bv.z, bv.w};
        #pragma unroll
        for (int r = 0; r < 4; r++)
            #pragma unroll
            for (int c = 0; c < 4; c++) acc[r][c] = fmaf(a[r], bb[c], acc[r][c]);
    }

    #pragma unroll
    for (int r = 0; r < 4; r++) {
        float xv2 = x2s[ty * 4 + r];
        #pragma unroll
        for (int c = 0; c < 4; c++)
            ts[ty * 4 + r][tx * 4 + c] = fmaf(-2.f, acc[r][c], xv2 + y2s[tx * 4 + c]);
    }
    __syncthreads();

    const size_t bbase = ((size_t)b) << 19;
    for (int idx = tid; idx < 127 * 64; idx += 256) {
        int kk = idx >> 6;
        int ii = idx & 63;
        int jj = kk - ii;
        if ((unsigned)jj < 64u)
            g_D[bbase + ((size_t)(i0 + j0 + kk) << 9) + (size_t)(i0 + ii)]
                = ts[ii][jj] * F_L2E;
    }
}

// ---------------------------------------------------------------------------
// Kernel 2: soft-DTW wavefront, warp-skewed, 4-step chunks, slim step.
// 64 blocks x 512 threads = 16 warps; thread t owns row i = t+1 (1-based).
// Warp-local step q = 0..543: lane l computes col j = q+1-l; diag kd = 32w+q.
// ring[w][col] = R[32w][col] (producer = warp w-1 lane31: col = q'-30).
// Producer stores aligned float2 pairs {q-31, q-30} at odd q; publishes
// prog[w+1] = min(4c-27, 512) after each 4-step chunk. Consumer chunk c needs
// cols <= 4c+4 -> waits prog >= min(4c+4, 512). Hop lag ~35 steps.
// Values carry an implicit log2(e) factor; softmin = 2x ex2 + 1x lg2.
// ---------------------------------------------------------------------------
__global__ __launch_bounds__(512) void dtw_kernel(float* __restrict__ out)
{
    __shared__ __align__(8) float ring[17][516];
    __shared__ int prog[17];

    const int b    = blockIdx.x;
    const int tid  = threadIdx.x;
    const int lane = tid & 31;
    const int w    = tid >> 5;
    const bool lane0  = (lane == 0);
    const bool lane31 = (lane == 31);

    for (int idx = tid; idx < 516; idx += 512) ring[0][idx] = BIGV;
    if (tid < 17) prog[tid] = 0;
    __syncthreads();

    const float* __restrict__ Dp    = g_D + (((size_t)b) << 19) + (size_t)tid;
    const float* __restrict__ ringR = ring[w];
    float*       __restrict__ ringW = ring[w + 1];
    const int offW = w << 5;
    const int kIdxMax = offW + 543;

    float rP1 = BIGV;
    float up_prev = BIGV;
    float bu_prev = (w == 0) ? 0.0f : BIGV;   // boundary col 0
    float wcarry  = BIGV;
    int pcache = 0;

    float dbuf[4], dnx[4];
    #pragma unroll
    for (int s = 0; s < 4; ++s) dbuf[s] = Dp[(size_t)(offW + s) << 9];

#define DTW_WAIT(C) do {                                                        \
        if (w) {                                                                \
            int need_ = 4 * (C) + 4; if (need_ > 512) need_ = 512;              \
            if (pcache < need_) {                                               \
                int p_ = ld_acquire_shared(&prog[w]);                           \
                while (p_ < need_) { __nanosleep(32);                           \
                                     p_ = ld_acquire_shared(&prog[w]); }        \
                pcache = p_;                                                    \
            }                                                                   \
        }                                                                       \
    } while (0)

#define DTW_PUB(C) do {                                                         \
        int pub_ = 4 * (C) - 27; if (pub_ > 512) pub_ = 512;                    \
        if (lane31 && pub_ > 0) st_release_shared(&prog[w + 1], pub_);          \
    } while (0)

// PH: 0 ramp-in, 1 steady, 2 ramp-out. PAR: 0 even q (carry), 1 odd q (pair store).
#define DTW_STEP(S, QV, PH, PAR) do {                                           \
        float d_  = dbuf[S];                                                    \
        float upv = __shfl_up_sync(0xffffffffu, rP1, 1);                        \
        int rc_ = (QV) + 1; if (PH == 2 && rc_ > 512) rc_ = 512;                \
        float bu  = ringR[rc_];                                                 \
        float up  = lane0 ? bu : upv;                                           \
        float dg  = lane0 ? bu_prev : up_prev;                                  \
        up_prev = upv; bu_prev = bu;                                            \
        float lo  = fminf(dg, rP1), hi = fmaxf(dg, rP1);                        \
        float mn  = fminf(lo, up);                                              \
        float mid = fminf(fmaxf(lo, up), hi);                                   \
        float mx  = fmaxf(hi, up);                                              \
        float t_  = ex2f_(mn - mid) + ex2f_(mn - mx);                           \
        float rn  = d_ + mn - lg2f_(1.0f + t_);                                 \
        if (PH == 0) rn = (lane <= (QV)) ? rn : BIGV;                           \
        if (PH == 2) rn = (lane >= (QV) - 511) ? rn : BIGV;                     \
        rP1 = rn;                                                               \
        if (PH == 2) { if ((QV) == 542 && tid == 511) out[b] = rn * F_LN2; }    \
        if (PAR == 0) { wcarry = rn; }                                          \
        else if (lane31) {                                                      \
            int cm1_ = (QV) - 31;                                               \
            if (PH != 0 || cm1_ >= 0)                                           \
                *(float2*)&ringW[cm1_] = make_float2(wcarry, rn);               \
        }                                                                       \
    } while (0)

#define DTW_PREFETCH(C, PH) do {                                                \
        int kb_ = offW + 4 * ((C) + 1);                                         \
        _Pragma("unroll")                                                       \
        for (int s_ = 0; s_ < 4; ++s_) {                                        \
            int kd_ = kb_ + s_;                                                 \
            if (PH == 2 && kd_ > kIdxMax) kd_ = kIdxMax;                        \
            dnx[s_] = Dp[(size_t)kd_ << 9];                                     \
        }                                                                       \
    } while (0)

#define DTW_ROT() do {                                                          \
        _Pragma("unroll")                                                       \
        for (int s_ = 0; s_ < 4; ++s_) dbuf[s_] = dnx[s_];                      \
    } while (0)

    // ---- ramp-in: chunks 0..7 (q = 0..31) ----
    #pragma unroll 1
    for (int c = 0; c < 8; ++c) {
        DTW_WAIT(c);
        DTW_PREFETCH(c, 0);
        DTW_STEP(0, 4 * c + 0, 0, 0);
        DTW_STEP(1, 4 * c + 1, 0, 1);
        DTW_STEP(2, 4 * c + 2, 0, 0);
        DTW_STEP(3, 4 * c + 3, 0, 1);
        DTW_ROT();
        DTW_PUB(c);
    }

    // ---- steady: chunks 8..127 (q = 32..511), all lanes valid ----
    #pragma unroll 1
    for (int c = 8; c < 128; ++c) {
        DTW_WAIT(c);
        DTW_PREFETCH(c, 1);
        DTW_STEP(0, 4 * c + 0, 1, 0);
        DTW_STEP(1, 4 * c + 1, 1, 1);
        DTW_STEP(2, 4 * c + 2, 1, 0);
        DTW_STEP(3, 4 * c + 3, 1, 1);
        DTW_ROT();
        DTW_PUB(c);
    }

    // ---- ramp-out: chunks 128..135 (q = 512..543); lane0 invalid -> no waits ----
    #pragma unroll 1
    for (int c = 128; c < 136; ++c) {
        DTW_PREFETCH(c, 2);
        DTW_STEP(0, 4 * c + 0, 2, 0);
        DTW_STEP(1, 4 * c + 1, 2, 1);
        DTW_STEP(2, 4 * c + 2, 2, 0);
        DTW_STEP(3, 4 * c + 3, 2, 1);
        DTW_ROT();
        DTW_PUB(c);
    }

#undef DTW_STEP
#undef DTW_PUB
#undef DTW_WAIT
#undef DTW_PREFETCH
#undef DTW_ROT
}

extern "C" void kernel_launch(void* const* d_in, const int* in_sizes, int n_in,
                              void* d_out, int out_size)
{
    const float* x = (const float*)d_in[0];
    const float* y = (const float*)d_in[1];
    float* out = (float*)d_out;

    dim3 g1(8, 8, 64);
    sqdist_kernel<<<g1, 256>>>(x, y);
    dtw_kernel<<<64, 512>>>(out);
}

// round 10
// speedup vs baseline: 1.2553x; 1.2553x over previous
#include <cuda_runtime.h>
#include <cuda_bf16.h>
#include <cstdint>

#define BIGV 10000000000.0f
#define F_L2E 1.4426950408889634f
#define F_LN2 0.6931471805599453f

// D (pre-scaled by log2(e)) in anti-diagonal-major layout:
// g_D[b][kd][i0] = log2e * D[b][i0][j0], kd = i0 + j0 (0-based), dims [64][1024][512].
__device__ float g_D[(size_t)64 * 1024 * 512];

__device__ __forceinline__ float ex2f_(float x) {
    float r; asm("ex2.approx.f32 %0, %1;" : "=f"(r) : "f"(x)); return r;
}
__device__ __forceinline__ float lg2f_(float x) {
    float r; asm("lg2.approx.f32 %0, %1;" : "=f"(r) : "f"(x)); return r;
}
__device__ __forceinline__ void st_release_shared(int* p, int v) {
    unsigned a = (unsigned)__cvta_generic_to_shared(p);
    asm volatile("st.release.cta.shared.b32 [%0], %1;" :: "r"(a), "r"(v) : "memory");
}
__device__ __forceinline__ int ld_acquire_shared(const int* p) {
    unsigned a = (unsigned)__cvta_generic_to_shared(p);
    int v; asm volatile("ld.acquire.cta.shared.b32 %0, [%1];" : "=r"(v) : "r"(a) : "memory");
    return v;
}

// ---------------------------------------------------------------------------
// Kernel 1: squared distances * log2e, written anti-diagonal-major.
// ---------------------------------------------------------------------------
__global__ __launch_bounds__(256) void sqdist_kernel(const float* __restrict__ x,
                                                     const float* __restrict__ y)
{
    __shared__ __align__(16) float xs[16][64];
    __shared__ __align__(16) float ys[16][64];
    __shared__ float x2s[64], y2s[64];
    __shared__ float ts[64][66];

    const int b   = blockIdx.z;
    const int i0  = blockIdx.y * 64;
    const int j0  = blockIdx.x * 64;
    const int tid = threadIdx.x;

    {
        int row = tid >> 2;
        int d0  = (tid & 3) * 4;
        float4 xv = *(const float4*)(x + ((size_t)(b * 512 + i0 + row)) * 16 + d0);
        xs[d0 + 0][row] = xv.x; xs[d0 + 1][row] = xv.y;
        xs[d0 + 2][row] = xv.z; xs[d0 + 3][row] = xv.w;
        float4 yv = *(const float4*)(y + ((size_t)(b * 512 + j0 + row)) * 16 + d0);
        ys[d0 + 0][row] = yv.x; ys[d0 + 1][row] = yv.y;
        ys[d0 + 2][row] = yv.z; ys[d0 + 3][row] = yv.w;
    }
    __syncthreads();

    if (tid < 64) {
        float s = 0.f;
        #pragma unroll
        for (int d = 0; d < 16; d++) s += xs[d][tid] * xs[d][tid];
        x2s[tid] = s;
    } else if (tid < 128) {
        int c = tid - 64;
        float s = 0.f;
        #pragma unroll
        for (int d = 0; d < 16; d++) s += ys[d][c] * ys[d][c];
        y2s[c] = s;
    }
    __syncthreads();

    const int tx = tid & 15;
    const int ty = tid >> 4;
    float acc[4][4];
    #pragma unroll
    for (int r = 0; r < 4; r++)
        #pragma unroll
        for (int c = 0; c < 4; c++) acc[r][c] = 0.f;

    #pragma unroll
    for (int d = 0; d < 16; d++) {
        float4 av = *(const float4*)&xs[d][ty * 4];
        float4 bv = *(const float4*)&ys[d][tx * 4];
        float a[4]  = {av.x, av.y, av.z, av.w};
        float bb[4] = {bv.x, bv.y, bv.z, bv.w};
        #pragma unroll
        for (int r = 0; r < 4; r++)
            #pragma unroll
            for (int c = 0; c < 4; c++) acc[r][c] = fmaf(a[r], bb[c], acc[r][c]);
    }

    #pragma unroll
    for (int r = 0; r < 4; r++) {
        float xv2 = x2s[ty * 4 + r];
        #pragma unroll
        for (int c = 0; c < 4; c++)
            ts[ty * 4 + r][tx * 4 + c] = fmaf(-2.f, acc[r][c], xv2 + y2s[tx * 4 + c]);
    }
    __syncthreads();

    const size_t bbase = ((size_t)b) << 19;
    for (int idx = tid; idx < 127 * 64; idx += 256) {
        int kk = idx >> 6;
        int ii = idx & 63;
        int jj = kk - ii;
        if ((unsigned)jj < 64u)
            g_D[bbase + ((size_t)(i0 + j0 + kk) << 9) + (size_t)(i0 + ii)]
                = ts[ii][jj] * F_L2E;
    }
}

// ---------------------------------------------------------------------------
// Kernel 2: soft-DTW wavefront, warp-skewed, REVERSED warp-role mapping.
// One block per batch, 512 threads = 16 warps. Row block wrev = 15 - w, so
// PRODUCERS (earlier rows) have HIGHER warp ids and win hi-wid-first
// arbitration over their spinning consumers. Thread covers row
// i = 32*wrev + lane + 1 (1-based); warp-local step q = 0..543, diag
// k = 32*wrev + 2 + q. One shfl + one LDS per step: dg(k)=up(k-1),
// bd(k)=bu(k-1). Boundary in ring[wrev+1]; progress per 8-step chunk
// (st.release / ld.acquire pure spin).
// Values carry an implicit log2(e) factor; softmin via 2x ex2 + 1x lg2.
// ---------------------------------------------------------------------------
__global__ __launch_bounds__(512) void dtw_kernel(float* __restrict__ out)
{
    __shared__ float ring[17][516];
    __shared__ int prog[17];

    const int b    = blockIdx.x;
    const int tid  = threadIdx.x;
    const int lane = tid & 31;
    const int w    = tid >> 5;
    const int wrev = 15 - w;             // row-block index (reversed priority)
    const int offW = wrev << 5;

    for (int idx = tid; idx < 516; idx += 512) ring[0][idx] = BIGV;
    if (tid < 17) prog[tid] = (tid == 0) ? 512 : 0;
    __syncthreads();

    const float* __restrict__ dp0   = g_D + (((size_t)b) << 19) + (size_t)(offW + lane);
    const float* __restrict__ ringR = ring[wrev];
    float*       __restrict__ ringW = ring[wrev + 1];
    const int kbeg = offW + 2;
    const int kIdxMax = offW + 543;       // max (k-2) index ever touched

    float rP1 = BIGV, rP2 = BIGV;
    float up_prev = BIGV;
    float bu_prev = (wrev == 0) ? 0.0f : BIGV;

    float dcur[8], dnx[8];
    #pragma unroll
    for (int s = 0; s < 8; ++s) dcur[s] = dp0[(size_t)(kbeg - 2 + s) << 9];

#define DTW_STEP(SIDX, Q, TU, DOVALID, VPRED, STORECHK) do {                   \
        float d_   = dcur[SIDX];                                               \
        float upv_ = __shfl_up_sync(0xffffffffu, rP1, 1);                      \
        float bu_  = ringR[(TU)];                                              \
        float dgv_ = (lane == 0) ? bu_prev : up_prev;                          \
        float upm_ = (lane == 0) ? bu_ : upv_;                                 \
        up_prev = upv_; bu_prev = bu_;                                         \
        float mn1_ = fminf(dgv_, upm_), mx1_ = fmaxf(dgv_, upm_);              \
        float mn_  = fminf(mn1_, rP1);                                         \
        float mid_ = fmaxf(mn1_, fminf(mx1_, rP1));                            \
        float mx_  = fmaxf(mx1_, rP1);                                         \
        float t2_  = ex2f_(mn_ - mid_) + ex2f_(mn_ - mx_);                     \
        float sm_  = lg2f_(1.0f + t2_);                                        \
        float rN_  = d_ + mn_ - sm_;                                           \
        if (DOVALID) rN_ = (VPRED) ? rN_ : BIGV;                               \
        rP2 = rP1; rP1 = rN_;                                                  \
        int tS_ = (Q) - 31;                                                    \
        if (lane == 31 && (!(STORECHK) || tS_ >= 0)) ringW[tS_] = rN_;         \
    } while (0)

    // ---- ramp-in: chunks 0..3 (q = 0..31) ----
    #pragma unroll 1
    for (int c = 0; c < 4; ++c) {
        if (wrev) {
            int need = 8 * c + 8;
            while (ld_acquire_shared(&prog[wrev]) < need) { }
        }
        int kn = kbeg + 8 * (c + 1) - 2;
        #pragma unroll
        for (int s = 0; s < 8; ++s) dnx[s] = dp0[(size_t)(kn + s) << 9];
        #pragma unroll
        for (int s = 0; s < 8; ++s) {
            int q = 8 * c + s;
            DTW_STEP(s, q, q, true, lane <= q, true);
        }
        #pragma unroll
        for (int s = 0; s < 8; ++s) dcur[s] = dnx[s];
        int pub = 8 * c - 23;
        if (lane == 31 && pub > 0) st_release_shared(&prog[wrev + 1], pub);
    }

    // ---- steady: chunks 4..63 (q = 32..511), all lanes valid ----
    #pragma unroll 1
    for (int c = 4; c < 64; ++c) {
        if (wrev) {
            int need = 8 * c + 8;
            while (ld_acquire_shared(&prog[wrev]) < need) { }
        }
        int kn = kbeg + 8 * (c + 1) - 2;
        #pragma unroll
        for (int s = 0; s < 8; ++s) dnx[s] = dp0[(size_t)(kn + s) << 9];
        #pragma unroll
        for (int s = 0; s < 8; ++s) {
            int q = 8 * c + s;
            DTW_STEP(s, q, q, false, true, false);
        }
        #pragma unroll
        for (int s = 0; s < 8; ++s) dcur[s] = dnx[s];
        int pub = 8 * c - 23;
        if (lane == 31) st_release_shared(&prog[wrev + 1], pub);
    }

    // ---- ramp-out: chunks 64..67 (q = 512..543); lane 0 never valid -> no waits ----
    #pragma unroll 1
    for (int c = 64; c < 68; ++c) {
        int kn = kbeg + 8 * (c + 1) - 2;
        #pragma unroll
        for (int s = 0; s < 8; ++s) {
            int kk = kn + s; if (kk > kIdxMax) kk = kIdxMax;
            dnx[s] = dp0[(size_t)kk << 9];
        }
        #pragma unroll
        for (int s = 0; s < 8; ++s) {
            int q  = 8 * c + s;
            int tu = q < 511 ? q : 511;
            DTW_STEP(s, q, tu, true, lane >= q - 511, false);
        }
        #pragma unroll
        for (int s = 0; s < 8; ++s) dcur[s] = dnx[s];
        int pub = 8 * c - 23; if (pub > 512) pub = 512;
        if (lane == 31) st_release_shared(&prog[wrev + 1], pub);
    }
#undef DTW_STEP

    // Last step q=543 is the pad step; rP2 = value at q=542 = R[512][512]
    // (row 512 -> wrev=15, lane=31 -> tid=31).
    if (wrev == 15 && lane == 31) out[b] = rP2 * F_LN2;
}

extern "C" void kernel_launch(void* const* d_in, const int* in_sizes, int n_in,
                              void* d_out, int out_size)
{
    const float* x = (const float*)d_in[0];
    const float* y = (const float*)d_in[1];
    float* out = (float*)d_out;

    dim3 g1(8, 8, 64);
    sqdist_kernel<<<g1, 256>>>(x, y);
    dtw_kernel<<<64, 512>>>(out);
}

// round 11
// speedup vs baseline: 1.2572x; 1.0015x over previous
#include <cuda_runtime.h>
#include <cuda_bf16.h>
#include <cstdint>

#define BIGV 10000000000.0f
#define F_L2E 1.4426950408889634f
#define F_LN2 0.6931471805599453f

// D (pre-scaled by log2(e)) in anti-diagonal-major layout:
// g_D[b][kd][i0] = log2e * D[b][i0][j0], kd = i0 + j0 (0-based), dims [64][1024][512].
__device__ float g_D[(size_t)64 * 1024 * 512];

__device__ __forceinline__ float ex2f_(float x) {
    float r; asm("ex2.approx.f32 %0, %1;" : "=f"(r) : "f"(x)); return r;
}
__device__ __forceinline__ float lg2f_(float x) {
    float r; asm("lg2.approx.f32 %0, %1;" : "=f"(r) : "f"(x)); return r;
}
__device__ __forceinline__ void st_release_shared(int* p, int v) {
    unsigned a = (unsigned)__cvta_generic_to_shared(p);
    asm volatile("st.release.cta.shared.b32 [%0], %1;" :: "r"(a), "r"(v) : "memory");
}
__device__ __forceinline__ int ld_acquire_shared(const int* p) {
    unsigned a = (unsigned)__cvta_generic_to_shared(p);
    int v; asm volatile("ld.acquire.cta.shared.b32 %0, [%1];" : "=r"(v) : "r"(a) : "memory");
    return v;
}

// ---------------------------------------------------------------------------
// Kernel 1: squared distances * log2e, written anti-diagonal-major.
// ---------------------------------------------------------------------------
__global__ __launch_bounds__(256) void sqdist_kernel(const float* __restrict__ x,
                                                     const float* __restrict__ y)
{
    __shared__ __align__(16) float xs[16][64];
    __shared__ __align__(16) float ys[16][64];
    __shared__ float x2s[64], y2s[64];
    __shared__ float ts[64][66];

    const int b   = blockIdx.z;
    const int i0  = blockIdx.y * 64;
    const int j0  = blockIdx.x * 64;
    const int tid = threadIdx.x;

    {
        int row = tid >> 2;
        int d0  = (tid & 3) * 4;
        float4 xv = *(const float4*)(x + ((size_t)(b * 512 + i0 + row)) * 16 + d0);
        xs[d0 + 0][row] = xv.x; xs[d0 + 1][row] = xv.y;
        xs[d0 + 2][row] = xv.z; xs[d0 + 3][row] = xv.w;
        float4 yv = *(const float4*)(y + ((size_t)(b * 512 + j0 + row)) * 16 + d0);
        ys[d0 + 0][row] = yv.x; ys[d0 + 1][row] = yv.y;
        ys[d0 + 2][row] = yv.z; ys[d0 + 3][row] = yv.w;
    }
    __syncthreads();

    if (tid < 64) {
        float s = 0.f;
        #pragma unroll
        for (int d = 0; d < 16; d++) s += xs[d][tid] * xs[d][tid];
        x2s[tid] = s;
    } else if (tid < 128) {
        int c = tid - 64;
        float s = 0.f;
        #pragma unroll
        for (int d = 0; d < 16; d++) s += ys[d][c] * ys[d][c];
        y2s[c] = s;
    }
    __syncthreads();

    const int tx = tid & 15;
    const int ty = tid >> 4;
    float acc[4][4];
    #pragma unroll
    for (int r = 0; r < 4; r++)
        #pragma unroll
        for (int c = 0; c < 4; c++) acc[r][c] = 0.f;

    #pragma unroll
    for (int d = 0; d < 16; d++) {
        float4 av = *(const float4*)&xs[d][ty * 4];
        float4 bv = *(const float4*)&ys[d][tx * 4];
        float a[4]  = {av.x, av.y, av.z, av.w};
        float bb[4] = {bv.x, bv.y, bv.z, bv.w};
        #pragma unroll
        for (int r = 0; r < 4; r++)
            #pragma unroll
            for (int c = 0; c < 4; c++) acc[r][c] = fmaf(a[r], bb[c], acc[r][c]);
    }

    #pragma unroll
    for (int r = 0; r < 4; r++) {
        float xv2 = x2s[ty * 4 + r];
        #pragma unroll
        for (int c = 0; c < 4; c++)
            ts[ty * 4 + r][tx * 4 + c] = fmaf(-2.f, acc[r][c], xv2 + y2s[tx * 4 + c]);
    }
    __syncthreads();

    const size_t bbase = ((size_t)b) << 19;
    for (int idx = tid; idx < 127 * 64; idx += 256) {
        int kk = idx >> 6;
        int ii = idx & 63;
        int jj = kk - ii;
        if ((unsigned)jj < 64u)
            g_D[bbase + ((size_t)(i0 + j0 + kk) << 9) + (size_t)(i0 + ii)]
                = ts[ii][jj] * F_L2E;
    }
}

// ---------------------------------------------------------------------------
// Kernel 2: soft-DTW wavefront, warp-skewed, REVERSED warp-role mapping.
// One block per batch, 512 threads = 16 warps. Row block wrev = 15 - w, so
// PRODUCERS (earlier rows) have HIGHER warp ids and win hi-wid-first
// arbitration over their spinning consumers. Thread covers row
// i = 32*wrev + lane + 1 (1-based); warp-local step q = 0..543, diag
// k = 32*wrev + 2 + q. One shfl + one LDS per step: dg(k)=up(k-1),
// bd(k)=bu(k-1). Boundary in ring[wrev+1]; progress per 8-step chunk
// (st.release / ld.acquire pure spin).
// Values carry an implicit log2(e) factor; softmin via 2x ex2 + 1x lg2.
// ---------------------------------------------------------------------------
__global__ __launch_bounds__(512) void dtw_kernel(float* __restrict__ out)
{
    __shared__ float ring[17][516];
    __shared__ int prog[17];

    const int b    = blockIdx.x;
    const int tid  = threadIdx.x;
    const int lane = tid & 31;
    const int w    = tid >> 5;
    const int wrev = 15 - w;             // row-block index (reversed priority)
    const int offW = wrev << 5;

    for (int idx = tid; idx < 516; idx += 512) ring[0][idx] = BIGV;
    if (tid < 17) prog[tid] = (tid == 0) ? 512 : 0;
    __syncthreads();

    const float* __restrict__ dp0   = g_D + (((size_t)b) << 19) + (size_t)(offW + lane);
    const float* __restrict__ ringR = ring[wrev];
    float*       __restrict__ ringW = ring[wrev + 1];
    const int kbeg = offW + 2;
    const int kIdxMax = offW + 543;       // max (k-2) index ever touched

    float rP1 = BIGV, rP2 = BIGV;
    float up_prev = BIGV;
    float bu_prev = (wrev == 0) ? 0.0f : BIGV;

    float dcur[8], dnx[8];
    #pragma unroll
    for (int s = 0; s < 8; ++s) dcur[s] = dp0[(size_t)(kbeg - 2 + s) << 9];

#define DTW_STEP(SIDX, Q, TU, DOVALID, VPRED, STORECHK) do {                   \
        float d_   = dcur[SIDX];                                               \
        float upv_ = __shfl_up_sync(0xffffffffu, rP1, 1);                      \
        float bu_  = ringR[(TU)];                                              \
        float dgv_ = (lane == 0) ? bu_prev : up_prev;                          \
        float upm_ = (lane == 0) ? bu_ : upv_;                                 \
        up_prev = upv_; bu_prev = bu_;                                         \
        float mn1_ = fminf(dgv_, upm_), mx1_ = fmaxf(dgv_, upm_);              \
        float mn_  = fminf(mn1_, rP1);                                         \
        float mid_ = fmaxf(mn1_, fminf(mx1_, rP1));                            \
        float mx_  = fmaxf(mx1_, rP1);                                         \
        float t2_  = ex2f_(mn_ - mid_) + ex2f_(mn_ - mx_);                     \
        float sm_  = lg2f_(1.0f + t2_);                                        \
        float rN_  = d_ + mn_ - sm_;                                           \
        if (DOVALID) rN_ = (VPRED) ? rN_ : BIGV;                               \
        rP2 = rP1; rP1 = rN_;                                                  \
        int tS_ = (Q) - 31;                                                    \
        if (lane == 31 && (!(STORECHK) || tS_ >= 0)) ringW[tS_] = rN_;         \
    } while (0)

    // ---- ramp-in: chunks 0..3 (q = 0..31) ----
    #pragma unroll 1
    for (int c = 0; c < 4; ++c) {
        if (wrev) {
            int need = 8 * c + 8;
            while (ld_acquire_shared(&prog[wrev]) < need) { }
        }
        int kn = kbeg + 8 * (c + 1) - 2;
        #pragma unroll
        for (int s = 0; s < 8; ++s) dnx[s] = dp0[(size_t)(kn + s) << 9];
        #pragma unroll
        for (int s = 0; s < 8; ++s) {
            int q = 8 * c + s;
            DTW_STEP(s, q, q, true, lane <= q, true);
        }
        #pragma unroll
        for (int s = 0; s < 8; ++s) dcur[s] = dnx[s];
        int pub = 8 * c - 23;
        if (lane == 31 && pub > 0) st_release_shared(&prog[wrev + 1], pub);
    }

    // ---- steady: chunks 4..63 (q = 32..511), all lanes valid ----
    #pragma unroll 1
    for (int c = 4; c < 64; ++c) {
        if (wrev) {
            int need = 8 * c + 8;
            while (ld_acquire_shared(&prog[wrev]) < need) { }
        }
        int kn = kbeg + 8 * (c + 1) - 2;
        #pragma unroll
        for (int s = 0; s < 8; ++s) dnx[s] = dp0[(size_t)(kn + s) << 9];
        #pragma unroll
        for (int s = 0; s < 8; ++s) {
            int q = 8 * c + s;
            DTW_STEP(s, q, q, false, true, false);
        }
        #pragma unroll
        for (int s = 0; s < 8; ++s) dcur[s] = dnx[s];
        int pub = 8 * c - 23;
        if (lane == 31) st_release_shared(&prog[wrev + 1], pub);
    }

    // ---- ramp-out: chunks 64..67 (q = 512..543); lane 0 never valid -> no waits ----
    #pragma unroll 1
    for (int c = 64; c < 68; ++c) {
        int kn = kbeg + 8 * (c + 1) - 2;
        #pragma unroll
        for (int s = 0; s < 8; ++s) {
            int kk = kn + s; if (kk > kIdxMax) kk = kIdxMax;
            dnx[s] = dp0[(size_t)kk << 9];
        }
        #pragma unroll
        for (int s = 0; s < 8; ++s) {
            int q  = 8 * c + s;
            int tu = q < 511 ? q : 511;
            DTW_STEP(s, q, tu, true, lane >= q - 511, false);
        }
        #pragma unroll
        for (int s = 0; s < 8; ++s) dcur[s] = dnx[s];
        int pub = 8 * c - 23; if (pub > 512) pub = 512;
        if (lane == 31) st_release_shared(&prog[wrev + 1], pub);
    }
#undef DTW_STEP

    // Last step q=543 is the pad step; rP2 = value at q=542 = R[512][512]
    // (row 512 -> wrev=15, lane=31 -> tid=31).
    if (wrev == 15 && lane == 31) out[b] = rP2 * F_LN2;
}

extern "C" void kernel_launch(void* const* d_in, const int* in_sizes, int n_in,
                              void* d_out, int out_size)
{
    const float* x = (const float*)d_in[0];
    const float* y = (const float*)d_in[1];
    float* out = (float*)d_out;

    dim3 g1(8, 8, 64);
    sqdist_kernel<<<g1, 256>>>(x, y);
    dtw_kernel<<<64, 512>>>(out);
}

// round 13
// speedup vs baseline: 1.2943x; 1.0295x over previous
#include <cuda_runtime.h>
#include <cuda_bf16.h>
#include <cstdint>

#define BIGV 10000000000.0f
#define F_L2E 1.4426950408889634f
#define F_LN2 0.6931471805599453f

// D (pre-scaled by log2(e)) in anti-diagonal-major layout:
// g_D[b][kd][i0] = log2e * D[b][i0][j0], kd = i0 + j0 (0-based), dims [64][1024][512].
__device__ float g_D[(size_t)64 * 1024 * 512];

__device__ __forceinline__ float ex2f_(float x) {
    float r; asm("ex2.approx.f32 %0, %1;" : "=f"(r) : "f"(x)); return r;
}
__device__ __forceinline__ float lg2f_(float x) {
    float r; asm("lg2.approx.f32 %0, %1;" : "=f"(r) : "f"(x)); return r;
}
__device__ __forceinline__ void st_release_shared(int* p, int v) {
    unsigned a = (unsigned)__cvta_generic_to_shared(p);
    asm volatile("st.release.cta.shared.b32 [%0], %1;" :: "r"(a), "r"(v) : "memory");
}
__device__ __forceinline__ int ld_acquire_shared(const int* p) {
    unsigned a = (unsigned)__cvta_generic_to_shared(p);
    int v; asm volatile("ld.acquire.cta.shared.b32 %0, [%1];" : "=r"(v) : "r"(a) : "memory");
    return v;
}

// ---------------------------------------------------------------------------
// Kernel 1: squared distances * log2e, written anti-diagonal-major.
// ---------------------------------------------------------------------------
__global__ __launch_bounds__(256) void sqdist_kernel(const float* __restrict__ x,
                                                     const float* __restrict__ y)
{
    __shared__ __align__(16) float xs[16][64];
    __shared__ __align__(16) float ys[16][64];
    __shared__ float x2s[64], y2s[64];
    __shared__ float ts[64][66];

    const int b   = blockIdx.z;
    const int i0  = blockIdx.y * 64;
    const int j0  = blockIdx.x * 64;
    const int tid = threadIdx.x;

    {
        int row = tid >> 2;
        int d0  = (tid & 3) * 4;
        float4 xv = *(const float4*)(x + ((size_t)(b * 512 + i0 + row)) * 16 + d0);
        xs[d0 + 0][row] = xv.x; xs[d0 + 1][row] = xv.y;
        xs[d0 + 2][row] = xv.z; xs[d0 + 3][row] = xv.w;
        float4 yv = *(const float4*)(y + ((size_t)(b * 512 + j0 + row)) * 16 + d0);
        ys[d0 + 0][row] = yv.x; ys[d0 + 1][row] = yv.y;
        ys[d0 + 2][row] = yv.z; ys[d0 + 3][row] = yv.w;
    }
    __syncthreads();

    if (tid < 64) {
        float s = 0.f;
        #pragma unroll
        for (int d = 0; d < 16; d++) s += xs[d][tid] * xs[d][tid];
        x2s[tid] = s;
    } else if (tid < 128) {
        int c = tid - 64;
        float s = 0.f;
        #pragma unroll
        for (int d = 0; d < 16; d++) s += ys[d][c] * ys[d][c];
        y2s[c] = s;
    }
    __syncthreads();

    const int tx = tid & 15;
    const int ty = tid >> 4;
    float acc[4][4];
    #pragma unroll
    for (int r = 0; r < 4; r++)
        #pragma unroll
        for (int c = 0; c < 4; c++) acc[r][c] = 0.f;

    #pragma unroll
    for (int d = 0; d < 16; d++) {
        float4 av = *(const float4*)&xs[d][ty * 4];
        float4 bv = *(const float4*)&ys[d][tx * 4];
        float a[4]  = {av.x, av.y, av.z, av.w};
        float bb[4] = {bv.x, bv.y, bv.z, bv.w};
        #pragma unroll
        for (int r = 0; r < 4; r++)
            #pragma unroll
            for (int c = 0; c < 4; c++) acc[r][c] = fmaf(a[r], bb[c], acc[r][c]);
    }

    #pragma unroll
    for (int r = 0; r < 4; r++) {
        float xv2 = x2s[ty * 4 + r];
        #pragma unroll
        for (int c = 0; c < 4; c++)
            ts[ty * 4 + r][tx * 4 + c] = fmaf(-2.f, acc[r][c], xv2 + y2s[tx * 4 + c]);
    }
    __syncthreads();

    const size_t bbase = ((size_t)b) << 19;
    for (int idx = tid; idx < 127 * 64; idx += 256) {
        int kk = idx >> 6;
        int ii = idx & 63;
        int jj = kk - ii;
        if ((unsigned)jj < 64u)
            g_D[bbase + ((size_t)(i0 + j0 + kk) << 9) + (size_t)(i0 + ii)]
                = ts[ii][jj] * F_L2E;
    }
}

// ---------------------------------------------------------------------------
// Kernel 2: soft-DTW wavefront, warp-skewed (best-known R3 configuration).
// One block per batch, 512 threads = 16 warps; thread t owns row i = t+1
// (1-based). Warp-local step q = 0..543 -> diag k = 32w+2+q, col j = q+1-lane.
// One shfl + one LDS per step: dg(k) = up(k-1), bd(k) = bu(k-1). Boundary in
// ring[w+1][t] (t = boundary col - 1); progress per 8-step chunk
// (st.release / ld.acquire with nanosleep backoff).
// Values carry an implicit log2(e) factor; softmin via 2x ex2 + 1x lg2.
// ---------------------------------------------------------------------------
__global__ __launch_bounds__(512) void dtw_kernel(float* __restrict__ out)
{
    __shared__ float ring[17][516];
    __shared__ int prog[17];

    const int b    = blockIdx.x;
    const int tid  = threadIdx.x;
    const int lane = tid & 31;
    const int w    = tid >> 5;

    for (int idx = tid; idx < 516; idx += 512) ring[0][idx] = BIGV;
    if (tid < 17) prog[tid] = 0;
    __syncthreads();

    const float* __restrict__ dp0   = g_D + (((size_t)b) << 19) + (size_t)tid;
    const float* __restrict__ ringR = ring[w];
    float*       __restrict__ ringW = ring[w + 1];

    const int kbeg    = (w << 5) + 2;
    const int kIdxMax = (w << 5) + 543;     // max (k-2) index ever touched

    float rP1 = BIGV;
    float up_prev = BIGV;
    float bu_prev = (w == 0) ? 0.0f : BIGV;

    float dcur[8], dnx[8];
    #pragma unroll
    for (int s = 0; s < 8; ++s) dcur[s] = dp0[(size_t)(kbeg + s - 2) << 9];

#define DTW_STEP(SIDX, Q, TU, DOVALID, VPRED, STORECHK, LAST) do {             \
        float d_   = dcur[SIDX];                                               \
        float upv_ = __shfl_up_sync(0xffffffffu, rP1, 1);                      \
        float bu_  = ringR[(TU)];                                              \
        float dgv_ = (lane == 0) ? bu_prev : up_prev;                          \
        float upm_ = (lane == 0) ? bu_ : upv_;                                 \
        up_prev = upv_; bu_prev = bu_;                                         \
        float mn1_ = fminf(dgv_, upm_), mx1_ = fmaxf(dgv_, upm_);              \
        float mn_  = fminf(mn1_, rP1);                                         \
        float mid_ = fmaxf(mn1_, fminf(mx1_, rP1));                            \
        float mx_  = fmaxf(mx1_, rP1);                                         \
        float t2_  = ex2f_(mn_ - mid_) + ex2f_(mn_ - mx_);                     \
        float sm_  = lg2f_(1.0f + t2_);                                        \
        float rN_  = d_ + mn_ - sm_;                                           \
        if (DOVALID) rN_ = (VPRED) ? rN_ : BIGV;                               \
        if (LAST) { if (tid == 511) out[b] = rN_ * F_LN2; }                    \
        rP1 = rN_;                                                             \
        int tS_ = (Q) - 31;                                                    \
        if (lane == 31 && (!(STORECHK) || tS_ >= 0)) ringW[tS_] = rN_;         \
    } while (0)

    // ---- ramp-in: chunks 0..3 (q = 0..31) ----
    #pragma unroll 1
    for (int c = 0; c < 4; ++c) {
        if (w) {
            int need = 8 * c + 8;
            if (ld_acquire_shared(&prog[w]) < need)
                while (ld_acquire_shared(&prog[w]) < need) __nanosleep(64);
        }
        int kn = kbeg + 8 * (c + 1) - 2;
        #pragma unroll
        for (int s = 0; s < 8; ++s) dnx[s] = dp0[(size_t)(kn + s) << 9];
        #pragma unroll
        for (int s = 0; s < 8; ++s) {
            int q = 8 * c + s;
            DTW_STEP(s, q, q, true, lane <= q, true, false);
        }
        #pragma unroll
        for (int s = 0; s < 8; ++s) dcur[s] = dnx[s];
        int pub = 8 * c - 23;
        if (lane == 31 && pub > 0) st_release_shared(&prog[w + 1], pub);
    }

    // ---- steady: chunks 4..63 (q = 32..511), all lanes valid ----
    #pragma unroll 1
    for (int c = 4; c < 64; ++c) {
        if (w) {
            int need = 8 * c + 8;        // <= 512 for all steady c; no clamp
            if (ld_acquire_shared(&prog[w]) < need)
                while (ld_acquire_shared(&prog[w]) < need) __nanosleep(64);
        }
        int kn = kbeg + 8 * (c + 1) - 2;
        #pragma unroll
        for (int s = 0; s < 8; ++s) dnx[s] = dp0[(size_t)(kn + s) << 9];
        #pragma unroll
        for (int s = 0; s < 8; ++s) {
            int q = 8 * c + s;
            DTW_STEP(s, q, q, false, true, false, false);
        }
        #pragma unroll
        for (int s = 0; s < 8; ++s) dcur[s] = dnx[s];
        int pub = 8 * c - 23;
        if (lane == 31) st_release_shared(&prog[w + 1], pub);
    }

    // ---- ramp-out: chunks 64..67 (q = 512..543); lane 0 never valid -> no waits ----
    #pragma unroll 1
    for (int c = 64; c < 68; ++c) {
        int kn = kbeg + 8 * (c + 1) - 2;
        #pragma unroll
        for (int s = 0; s < 8; ++s) {
            int kk = kn + s; if (kk > kIdxMax) kk = kIdxMax;
            dnx[s] = dp0[(size_t)kk << 9];
        }
        #pragma unroll
        for (int s = 0; s < 8; ++s) {
            int q  = 8 * c + s;
            int tu = q < 511 ? q : 511;
            // q == 542: tid 511 computes R[512][512] -> output.
            DTW_STEP(s, q, tu, true, lane >= q - 511, false, q == 542);
        }
        #pragma unroll
        for (int s = 0; s < 8; ++s) dcur[s] = dnx[s];
        int pub = 8 * c - 23; if (pub > 512) pub = 512;
        if (lane == 31) st_release_shared(&prog[w + 1], pub);
    }
#undef DTW_STEP
}

extern "C" void kernel_launch(void* const* d_in, const int* in_sizes, int n_in,
                              void* d_out, int out_size)
{
    const float* x = (const float*)d_in[0];
    const float* y = (const float*)d_in[1];
    float* out = (float*)d_out;

    dim3 g1(8, 8, 64);
    sqdist_kernel<<<g1, 256>>>(x, y);
    dtw_kernel<<<64, 512>>>(out);
}